// round 1
// baseline (speedup 1.0000x reference)
#include <cuda_runtime.h>
#include <math.h>

#define B_ 8
#define T_ 64
#define N_ 256
#define H_ 8
#define D_ 64
#define FEAT 512
#define TOKENS (B_*T_*N_)          /* 131072 */
#define ELEMS  (TOKENS*FEAT)       /* 67108864 */

// ---------------------------------------------------------------------------
// Scratch (device globals — no cudaMalloc allowed)
// ---------------------------------------------------------------------------
__device__ float g_s0[ELEMS];   // xl+te, later ff2
__device__ float g_s1[ELEMS];   // xh+te, later attn-out
__device__ float g_s2[ELEMS];   // q, later ff1
__device__ float g_s3[ELEMS];   // k, later "out" (Wo result)
__device__ float g_s4[ELEMS];   // v, later val

// ---------------------------------------------------------------------------
// Elementwise: s0 = xl + te ; s1 = xh + te
// ---------------------------------------------------------------------------
__global__ __launch_bounds__(256)
void add_te_kernel(const float4* __restrict__ xl, const float4* __restrict__ xh,
                   const float4* __restrict__ te,
                   float4* __restrict__ o0, float4* __restrict__ o1)
{
    int i = blockIdx.x * 256 + threadIdx.x;
    float4 t = te[i];
    float4 a = xl[i];
    float4 b = xh[i];
    o0[i] = make_float4(a.x + t.x, a.y + t.y, a.z + t.z, a.w + t.w);
    o1[i] = make_float4(b.x + t.x, b.y + t.y, b.z + t.z, b.w + t.w);
}

// ---------------------------------------------------------------------------
// SGEMM: C[M,512] = A[M,512] @ W[512,512] + bias, optional ReLU
// Block tile 128x128, K-tile 16, 256 threads, 8x8 per-thread register tile.
// ---------------------------------------------------------------------------
__global__ __launch_bounds__(256, 2)
void gemm512(const float* __restrict__ A, const float* __restrict__ W,
             const float* __restrict__ bias, float* __restrict__ C, int relu)
{
    __shared__ float As[16 * 132];   // [k][m], padded (132 keeps 16B align, spreads banks)
    __shared__ float Bs[16 * 132];   // [k][n], padded

    const int tid = threadIdx.x;
    const int m0 = blockIdx.y * 128;
    const int n0 = blockIdx.x * 128;
    const int tx = tid & 15;   // n sub-tile (8 cols)
    const int ty = tid >> 4;   // m sub-tile (8 rows)

    float acc[8][8];
#pragma unroll
    for (int i = 0; i < 8; i++)
#pragma unroll
        for (int j = 0; j < 8; j++) acc[i][j] = 0.f;

    for (int kt = 0; kt < 32; kt++) {
        // Load A tile 128x16 (float4 along K), store transposed [k][m]
#pragma unroll
        for (int u = 0; u < 2; u++) {
            int idx = tid + u * 256;          // 0..511
            int row = idx >> 2;               // 0..127
            int kq  = idx & 3;                // k quad
            float4 va = *(const float4*)(A + (size_t)(m0 + row) * 512 + kt * 16 + kq * 4);
            As[(kq * 4 + 0) * 132 + row] = va.x;
            As[(kq * 4 + 1) * 132 + row] = va.y;
            As[(kq * 4 + 2) * 132 + row] = va.z;
            As[(kq * 4 + 3) * 132 + row] = va.w;
        }
        // Load B tile 16x128 (float4 along N), store direct [k][n]
#pragma unroll
        for (int u = 0; u < 2; u++) {
            int idx = tid + u * 256;          // 0..511
            int kr = idx >> 5;                // 0..15
            int nq = idx & 31;                // 0..31
            float4 vb = *(const float4*)(W + (size_t)(kt * 16 + kr) * 512 + n0 + nq * 4);
            *(float4*)(Bs + kr * 132 + nq * 4) = vb;
        }
        __syncthreads();

#pragma unroll
        for (int k = 0; k < 16; k++) {
            float4 a0 = *(float4*)(As + k * 132 + ty * 8);
            float4 a1 = *(float4*)(As + k * 132 + ty * 8 + 4);
            float4 b0 = *(float4*)(Bs + k * 132 + tx * 8);
            float4 b1 = *(float4*)(Bs + k * 132 + tx * 8 + 4);
            float a[8] = {a0.x, a0.y, a0.z, a0.w, a1.x, a1.y, a1.z, a1.w};
            float b[8] = {b0.x, b0.y, b0.z, b0.w, b1.x, b1.y, b1.z, b1.w};
#pragma unroll
            for (int i = 0; i < 8; i++)
#pragma unroll
                for (int j = 0; j < 8; j++)
                    acc[i][j] += a[i] * b[j];
        }
        __syncthreads();
    }

    float bv[8];
#pragma unroll
    for (int j = 0; j < 8; j++) bv[j] = bias[n0 + tx * 8 + j];

#pragma unroll
    for (int i = 0; i < 8; i++) {
        float c[8];
#pragma unroll
        for (int j = 0; j < 8; j++) {
            float x = acc[i][j] + bv[j];
            if (relu) x = fmaxf(x, 0.f);
            c[j] = x;
        }
        float* cp = C + (size_t)(m0 + ty * 8 + i) * 512 + n0 + tx * 8;
        *(float4*)(cp)     = make_float4(c[0], c[1], c[2], c[3]);
        *(float4*)(cp + 4) = make_float4(c[4], c[5], c[6], c[7]);
    }
}

// ---------------------------------------------------------------------------
// Causal attention per (b, n, h): T=64, D=64. One CTA per head instance.
// Masked BEFORE scaling (matches reference): masked logit = -32767/8.
// ---------------------------------------------------------------------------
__global__ __launch_bounds__(256)
void attn64(const float* __restrict__ q, const float* __restrict__ k,
            const float* __restrict__ v, float* __restrict__ out)
{
    __shared__ float Qs[64 * 64];
    __shared__ float Ks[64 * 64];   // XOR-swizzled rows for conflict-free column reads
    __shared__ float Vs[64 * 64];

    const int idx = blockIdx.x;
    const int h = idx & 7;
    const int n = (idx >> 3) & 255;
    const int b = idx >> 11;
    const size_t base = ((size_t)(b * T_) * N_ + n) * FEAT + h * D_;
    const int tid = threadIdx.x;
    const size_t tstride = (size_t)N_ * FEAT;   // 131072

    for (int i = tid; i < 4096; i += 256) {
        int t = i >> 6, d = i & 63;
        size_t off = base + (size_t)t * tstride + d;
        Qs[i] = q[off];
        Ks[t * 64 + (d ^ (t & 31))] = k[off];
        Vs[i] = v[off];
    }
    __syncthreads();

    const int w = tid >> 5;
    const int l = tid & 31;
    const float NEG8 = -4095.875f;   // (-2^15+1)/sqrt(64)

#pragma unroll
    for (int r = 0; r < 8; r++) {
        int t = w * 8 + r;
        float s0 = 0.f, s1 = 0.f;
#pragma unroll
        for (int d = 0; d < 64; d++) {
            float qd = Qs[t * 64 + d];
            s0 += qd * Ks[l * 64 + (d ^ l)];
            s1 += qd * Ks[(l + 32) * 64 + (d ^ l)];
        }
        float l0 = (l      <= t) ? s0 * 0.125f : NEG8;
        float l1 = (l + 32 <= t) ? s1 * 0.125f : NEG8;
        float m = fmaxf(l0, l1);
#pragma unroll
        for (int o = 16; o; o >>= 1) m = fmaxf(m, __shfl_xor_sync(0xffffffffu, m, o));
        float e0 = __expf(l0 - m), e1 = __expf(l1 - m);
        float sum = e0 + e1;
#pragma unroll
        for (int o = 16; o; o >>= 1) sum += __shfl_xor_sync(0xffffffffu, sum, o);
        float inv = 1.f / sum;
        float p0 = e0 * inv, p1 = e1 * inv;

        float a0 = 0.f, a1 = 0.f;
#pragma unroll
        for (int s = 0; s < 32; s++) {
            float ps = __shfl_sync(0xffffffffu, p0, s);
            a0 += ps * Vs[s * 64 + l];
            a1 += ps * Vs[s * 64 + l + 32];
        }
#pragma unroll
        for (int s = 0; s < 32; s++) {
            float ps = __shfl_sync(0xffffffffu, p1, s);
            a0 += ps * Vs[(s + 32) * 64 + l];
            a1 += ps * Vs[(s + 32) * 64 + l + 32];
        }
        size_t ooff = base + (size_t)t * tstride;
        out[ooff + l]      = a0;
        out[ooff + l + 32] = a1;
    }
}

// ---------------------------------------------------------------------------
// out = LayerNorm(a + b), eps=1e-5, no affine. One warp per 512-dim row.
// ---------------------------------------------------------------------------
__global__ __launch_bounds__(256)
void add_ln(const float* __restrict__ a, const float* __restrict__ b,
            float* __restrict__ out)
{
    int row = blockIdx.x * 8 + (threadIdx.x >> 5);
    int l = threadIdx.x & 31;
    const float4* pa = (const float4*)(a + (size_t)row * 512);
    const float4* pb = (const float4*)(b + (size_t)row * 512);

    float4 x[4];
    float s = 0.f;
#pragma unroll
    for (int i = 0; i < 4; i++) {
        float4 u = pa[l + i * 32], w = pb[l + i * 32];
        x[i] = make_float4(u.x + w.x, u.y + w.y, u.z + w.z, u.w + w.w);
        s += x[i].x + x[i].y + x[i].z + x[i].w;
    }
#pragma unroll
    for (int o = 16; o; o >>= 1) s += __shfl_xor_sync(0xffffffffu, s, o);
    float mean = s * (1.f / 512.f);

    float vs = 0.f;
#pragma unroll
    for (int i = 0; i < 4; i++) {
        float dx = x[i].x - mean, dy = x[i].y - mean, dz = x[i].z - mean, dw = x[i].w - mean;
        vs += dx * dx + dy * dy + dz * dz + dw * dw;
    }
#pragma unroll
    for (int o = 16; o; o >>= 1) vs += __shfl_xor_sync(0xffffffffu, vs, o);
    float invstd = rsqrtf(vs * (1.f / 512.f) + 1e-5f);

    float4* po = (float4*)(out + (size_t)row * 512);
#pragma unroll
    for (int i = 0; i < 4; i++) {
        po[l + i * 32] = make_float4((x[i].x - mean) * invstd, (x[i].y - mean) * invstd,
                                     (x[i].z - mean) * invstd, (x[i].w - mean) * invstd);
    }
}

// ---------------------------------------------------------------------------
// Launch pipeline (graph-capturable: launches only)
// ---------------------------------------------------------------------------
extern "C" void kernel_launch(void* const* d_in, const int* in_sizes, int n_in,
                              void* d_out, int out_size)
{
    const float* xl = (const float*)d_in[0];
    const float* xh = (const float*)d_in[1];
    const float* te = (const float*)d_in[2];
    const float* Wq = (const float*)d_in[3];
    const float* bq = (const float*)d_in[4];
    const float* Wk = (const float*)d_in[5];
    const float* bk = (const float*)d_in[6];
    const float* Wv = (const float*)d_in[7];
    const float* bv = (const float*)d_in[8];
    const float* Wo = (const float*)d_in[9];
    const float* bo = (const float*)d_in[10];
    const float* W1 = (const float*)d_in[11];
    const float* b1 = (const float*)d_in[12];
    const float* W2 = (const float*)d_in[13];
    const float* b2 = (const float*)d_in[14];
    float* out = (float*)d_out;

    float *s0, *s1, *s2, *s3, *s4;
    cudaGetSymbolAddress((void**)&s0, g_s0);
    cudaGetSymbolAddress((void**)&s1, g_s1);
    cudaGetSymbolAddress((void**)&s2, g_s2);
    cudaGetSymbolAddress((void**)&s3, g_s3);
    cudaGetSymbolAddress((void**)&s4, g_s4);

    const dim3 gg(4, 1024);          // N/128 x M/128
    const int nadd = ELEMS / 4 / 256; // 65536 blocks

    // s0 = xl+te, s1 = xh+te
    add_te_kernel<<<nadd, 256>>>((const float4*)xl, (const float4*)xh,
                                 (const float4*)te, (float4*)s0, (float4*)s1);
    // q, k, v
    gemm512<<<gg, 256>>>(s0, Wq, bq, s2, 0);
    gemm512<<<gg, 256>>>(s1, Wk, bk, s3, 1);
    gemm512<<<gg, 256>>>(s1, Wv, bv, s4, 1);
    // attention -> s1
    attn64<<<B_ * N_ * H_, 256>>>(s2, s3, s4, s1);
    // out = attn @ Wo + bo -> s3
    gemm512<<<gg, 256>>>(s1, Wo, bo, s3, 0);
    // val = LN(out + xl2) -> s4
    add_ln<<<TOKENS / 8, 256>>>(s3, s0, s4);
    // ff1 = relu(val @ W1 + b1) -> s2
    gemm512<<<gg, 256>>>(s4, W1, b1, s2, 1);
    // ff2 = ff1 @ W2 + b2 -> s0
    gemm512<<<gg, 256>>>(s2, W2, b2, s0, 0);
    // out = LN(ff2 + val)
    add_ln<<<TOKENS / 8, 256>>>(s0, s4, out);
}

// round 3
// speedup vs baseline: 1.9055x; 1.9055x over previous
#include <cuda_runtime.h>
#include <cuda_bf16.h>
#include <math.h>
#include <stdint.h>

#define B_ 8
#define T_ 64
#define N_ 256
#define H_ 8
#define D_ 64
#define FEAT 512
#define TOKENS (B_*T_*N_)          /* 131072 */
#define ELEMS  (TOKENS*FEAT)       /* 67108864 */
#define WSZ    (512*512)

// ---------------------------------------------------------------------------
// Scratch (device globals — no cudaMalloc allowed)
// ---------------------------------------------------------------------------
__device__ float g_s0[ELEMS];
__device__ float g_s1[ELEMS];
__device__ float g_s2[ELEMS];
__device__ float g_s3[ELEMS];
__device__ float g_s4[ELEMS];
__device__ float g_wt[6 * WSZ];   // K-major (transposed) weights

// ---------------------------------------------------------------------------
// Helpers
// ---------------------------------------------------------------------------
__device__ __forceinline__ uint32_t smem_u32(const void* p) {
    uint32_t a;
    asm("{ .reg .u64 t; cvta.to.shared.u64 t, %1; cvt.u32.u64 %0, t; }" : "=r"(a) : "l"(p));
    return a;
}

__device__ __forceinline__ uint32_t pack_bf2(float x, float y) {
    __nv_bfloat162 h = __floats2bfloat162_rn(x, y);
    return *(uint32_t*)&h;
}

__device__ __forceinline__ void ldsm4(uint32_t addr, uint32_t* r) {
    asm volatile("ldmatrix.sync.aligned.m8n8.x4.shared.b16 {%0,%1,%2,%3}, [%4];"
                 : "=r"(r[0]), "=r"(r[1]), "=r"(r[2]), "=r"(r[3]) : "r"(addr));
}

__device__ __forceinline__ void mma_bf16(float* d, const uint32_t* a,
                                         uint32_t b0, uint32_t b1) {
    asm volatile(
        "mma.sync.aligned.m16n8k16.row.col.f32.bf16.bf16.f32 "
        "{%0,%1,%2,%3}, {%4,%5,%6,%7}, {%8,%9}, {%0,%1,%2,%3};"
        : "+f"(d[0]), "+f"(d[1]), "+f"(d[2]), "+f"(d[3])
        : "r"(a[0]), "r"(a[1]), "r"(a[2]), "r"(a[3]), "r"(b0), "r"(b1));
}

// ---------------------------------------------------------------------------
// Weight transpose: Wt[n][k] = W[k][n]  (512x512)
// ---------------------------------------------------------------------------
__global__ __launch_bounds__(256)
void transpose512(const float* __restrict__ W, float* __restrict__ Wt)
{
    __shared__ float t[32][33];
    int bx = blockIdx.x * 32, by = blockIdx.y * 32;
#pragma unroll
    for (int r = 0; r < 32; r += 8)
        t[threadIdx.y + r][threadIdx.x] =
            W[(size_t)(by + threadIdx.y + r) * 512 + bx + threadIdx.x];
    __syncthreads();
#pragma unroll
    for (int r = 0; r < 32; r += 8)
        Wt[(size_t)(bx + threadIdx.y + r) * 512 + by + threadIdx.x] =
            t[threadIdx.x][threadIdx.y + r];
}

// ---------------------------------------------------------------------------
// Elementwise: s0 = xl + te ; s1 = xh + te
// ---------------------------------------------------------------------------
__global__ __launch_bounds__(256)
void add_te_kernel(const float4* __restrict__ xl, const float4* __restrict__ xh,
                   const float4* __restrict__ te,
                   float4* __restrict__ o0, float4* __restrict__ o1)
{
    int i = blockIdx.x * 256 + threadIdx.x;
    float4 t = te[i];
    float4 a = xl[i];
    float4 b = xh[i];
    o0[i] = make_float4(a.x + t.x, a.y + t.y, a.z + t.z, a.w + t.w);
    o1[i] = make_float4(b.x + t.x, b.y + t.y, b.z + t.z, b.w + t.w);
}

// ---------------------------------------------------------------------------
// 3xBF16 tensor-core GEMM: C[M,512] = A[M,512]@W + bias (+ReLU), fp32 acc.
// CTA tile 128x128, 128 threads (4 warps, 64x64 warp tiles), K chunks of 32.
// Bt is K-major (Bt[n][k] = W[k][n]). Split a = hi + lo (bf16 each);
// acc += Ah*Bh + Ah*Bl + Al*Bh.
// smem tiles: rows of 32 bf16 (64B), 16B-chunk XOR swizzle for ldmatrix.
// ---------------------------------------------------------------------------
__global__ __launch_bounds__(128, 2)
void gemm_mma(const float* __restrict__ A, const float* __restrict__ Bt,
              const float* __restrict__ bias, float* __restrict__ C, int relu)
{
    __shared__ __align__(128) unsigned char smem[32768];
    // layout: Ah[0,8K) Al[8K,16K) Bh[16K,24K) Bl[24K,32K)
    const uint32_t sb  = smem_u32(smem);
    const uint32_t sAh = sb, sAl = sb + 8192, sBh = sb + 16384, sBl = sb + 24576;

    const int tid  = threadIdx.x;
    const int lane = tid & 31;
    const int warp = tid >> 5;
    const int wm = warp >> 1, wn = warp & 1;
    const int m0 = blockIdx.y * 128;
    const int n0 = blockIdx.x * 128;

    const float* Ab = A  + (size_t)m0 * 512;
    const float* Bb = Bt + (size_t)n0 * 512;

    float acc[4][8][4];
#pragma unroll
    for (int i = 0; i < 4; i++)
#pragma unroll
        for (int j = 0; j < 8; j++)
#pragma unroll
            for (int k = 0; k < 4; k++) acc[i][j][k] = 0.f;

    // Per-thread ldmatrix row components (constant across chunks)
    const int rA_base = wm * 64 + (lane & 7) + ((lane >> 3) & 1) * 8;  // + mt*16
    const uint32_t kbA = ((lane >> 4) & 1) * 16;                        // + ks*32
    const int rB_base = wn * 64 + (lane & 7) + ((lane >> 4) & 1) * 8;  // + p*16
    const uint32_t kbB = ((lane >> 3) & 1) * 16;                        // + ks*32

    for (int c = 0; c < 16; c++) {
        __syncthreads();
        // ---- fill: 128x32 fp32 A and B -> bf16 hi/lo tiles, swizzled ----
#pragma unroll
        for (int j = 0; j < 8; j++) {
            int lin = tid + j * 128;
            int row = lin >> 3;
            int q   = lin & 7;
            size_t g = (size_t)row * 512 + c * 32 + q * 4;
            float4 va = *(const float4*)(Ab + g);
            float4 vb = *(const float4*)(Bb + g);
            uint32_t kb  = q * 8;
            uint32_t off = row * 64 + ((kb & 48) ^ (((row >> 1) & 3) << 4)) + (kb & 8);

            uint32_t ah0 = pack_bf2(va.x, va.y);
            uint32_t ah1 = pack_bf2(va.z, va.w);
            __nv_bfloat162* ph;
            ph = (__nv_bfloat162*)&ah0;
            float alx = va.x - __low2float(*ph), aly = va.y - __high2float(*ph);
            ph = (__nv_bfloat162*)&ah1;
            float alz = va.z - __low2float(*ph), alw = va.w - __high2float(*ph);

            uint32_t bh0 = pack_bf2(vb.x, vb.y);
            uint32_t bh1 = pack_bf2(vb.z, vb.w);
            ph = (__nv_bfloat162*)&bh0;
            float blx = vb.x - __low2float(*ph), bly = vb.y - __high2float(*ph);
            ph = (__nv_bfloat162*)&bh1;
            float blz = vb.z - __low2float(*ph), blw = vb.w - __high2float(*ph);

            *(uint2*)(smem + (off))          = make_uint2(ah0, ah1);
            *(uint2*)(smem + (off + 8192))   = make_uint2(pack_bf2(alx, aly), pack_bf2(alz, alw));
            *(uint2*)(smem + (off + 16384))  = make_uint2(bh0, bh1);
            *(uint2*)(smem + (off + 24576))  = make_uint2(pack_bf2(blx, bly), pack_bf2(blz, blw));
        }
        __syncthreads();

        // ---- compute: 2 k16 steps ----
#pragma unroll
        for (int ks = 0; ks < 2; ks++) {
            uint32_t ah[4][4], al[4][4], bh[4][4], bl[4][4];
#pragma unroll
            for (int mt = 0; mt < 4; mt++) {
                int r = rA_base + mt * 16;
                uint32_t kb = kbA + ks * 32;
                uint32_t off = r * 64 + (kb ^ (((r >> 1) & 3) << 4));
                ldsm4(sAh + off, ah[mt]);
                ldsm4(sAl + off, al[mt]);
            }
#pragma unroll
            for (int p = 0; p < 4; p++) {
                int r = rB_base + p * 16;
                uint32_t kb = kbB + ks * 32;
                uint32_t off = r * 64 + (kb ^ (((r >> 1) & 3) << 4));
                ldsm4(sBh + off, bh[p]);
                ldsm4(sBl + off, bl[p]);
            }
#pragma unroll
            for (int mt = 0; mt < 4; mt++)
#pragma unroll
                for (int nt = 0; nt < 8; nt++) {
                    int p = nt >> 1, h = (nt & 1) * 2;
                    mma_bf16(acc[mt][nt], ah[mt], bh[p][h], bh[p][h + 1]);
                    mma_bf16(acc[mt][nt], ah[mt], bl[p][h], bl[p][h + 1]);
                    mma_bf16(acc[mt][nt], al[mt], bh[p][h], bh[p][h + 1]);
                }
        }
    }

    // ---- epilogue: bias (+relu), direct fp32 stores ----
#pragma unroll
    for (int mt = 0; mt < 4; mt++) {
        int row = m0 + wm * 64 + mt * 16 + (lane >> 2);
#pragma unroll
        for (int nt = 0; nt < 8; nt++) {
            int col = n0 + wn * 64 + nt * 8 + (lane & 3) * 2;
            float2 bb = __ldg((const float2*)(bias + col));
            float v0 = acc[mt][nt][0] + bb.x;
            float v1 = acc[mt][nt][1] + bb.y;
            float v2 = acc[mt][nt][2] + bb.x;
            float v3 = acc[mt][nt][3] + bb.y;
            if (relu) {
                v0 = fmaxf(v0, 0.f); v1 = fmaxf(v1, 0.f);
                v2 = fmaxf(v2, 0.f); v3 = fmaxf(v3, 0.f);
            }
            *(float2*)(C + (size_t)row * 512 + col)       = make_float2(v0, v1);
            *(float2*)(C + (size_t)(row + 8) * 512 + col) = make_float2(v2, v3);
        }
    }
}

// ---------------------------------------------------------------------------
// Causal attention per (b, n, h): T=64, D=64. One CTA per head instance.
// Masked BEFORE scaling (matches reference): masked logit = -32767/8.
// ---------------------------------------------------------------------------
__global__ __launch_bounds__(256)
void attn64(const float* __restrict__ q, const float* __restrict__ k,
            const float* __restrict__ v, float* __restrict__ out)
{
    __shared__ float Qs[64 * 64];
    __shared__ float Ks[64 * 64];
    __shared__ float Vs[64 * 64];

    const int idx = blockIdx.x;
    const int h = idx & 7;
    const int n = (idx >> 3) & 255;
    const int b = idx >> 11;
    const size_t base = ((size_t)(b * T_) * N_ + n) * FEAT + h * D_;
    const int tid = threadIdx.x;
    const size_t tstride = (size_t)N_ * FEAT;

    for (int i = tid; i < 4096; i += 256) {
        int t = i >> 6, d = i & 63;
        size_t off = base + (size_t)t * tstride + d;
        Qs[i] = q[off];
        Ks[t * 64 + (d ^ (t & 31))] = k[off];
        Vs[i] = v[off];
    }
    __syncthreads();

    const int w = tid >> 5;
    const int l = tid & 31;
    const float NEG8 = -4095.875f;

#pragma unroll
    for (int r = 0; r < 8; r++) {
        int t = w * 8 + r;
        float s0 = 0.f, s1 = 0.f;
#pragma unroll
        for (int d = 0; d < 64; d++) {
            float qd = Qs[t * 64 + d];
            s0 += qd * Ks[l * 64 + (d ^ l)];
            s1 += qd * Ks[(l + 32) * 64 + (d ^ l)];
        }
        float l0 = (l      <= t) ? s0 * 0.125f : NEG8;
        float l1 = (l + 32 <= t) ? s1 * 0.125f : NEG8;
        float m = fmaxf(l0, l1);
#pragma unroll
        for (int o = 16; o; o >>= 1) m = fmaxf(m, __shfl_xor_sync(0xffffffffu, m, o));
        float e0 = __expf(l0 - m), e1 = __expf(l1 - m);
        float sum = e0 + e1;
#pragma unroll
        for (int o = 16; o; o >>= 1) sum += __shfl_xor_sync(0xffffffffu, sum, o);
        float inv = 1.f / sum;
        float p0 = e0 * inv, p1 = e1 * inv;

        float a0 = 0.f, a1 = 0.f;
#pragma unroll
        for (int s = 0; s < 32; s++) {
            float ps = __shfl_sync(0xffffffffu, p0, s);
            a0 += ps * Vs[s * 64 + l];
            a1 += ps * Vs[s * 64 + l + 32];
        }
#pragma unroll
        for (int s = 0; s < 32; s++) {
            float ps = __shfl_sync(0xffffffffu, p1, s);
            a0 += ps * Vs[(s + 32) * 64 + l];
            a1 += ps * Vs[(s + 32) * 64 + l + 32];
        }
        size_t ooff = base + (size_t)t * tstride;
        out[ooff + l]      = a0;
        out[ooff + l + 32] = a1;
    }
}

// ---------------------------------------------------------------------------
// out = LayerNorm(a + b), eps=1e-5, no affine. One warp per 512-dim row.
// ---------------------------------------------------------------------------
__global__ __launch_bounds__(256)
void add_ln(const float* __restrict__ a, const float* __restrict__ b,
            float* __restrict__ out)
{
    int row = blockIdx.x * 8 + (threadIdx.x >> 5);
    int l = threadIdx.x & 31;
    const float4* pa = (const float4*)(a + (size_t)row * 512);
    const float4* pb = (const float4*)(b + (size_t)row * 512);

    float4 x[4];
    float s = 0.f;
#pragma unroll
    for (int i = 0; i < 4; i++) {
        float4 u = pa[l + i * 32], w = pb[l + i * 32];
        x[i] = make_float4(u.x + w.x, u.y + w.y, u.z + w.z, u.w + w.w);
        s += x[i].x + x[i].y + x[i].z + x[i].w;
    }
#pragma unroll
    for (int o = 16; o; o >>= 1) s += __shfl_xor_sync(0xffffffffu, s, o);
    float mean = s * (1.f / 512.f);

    float vs = 0.f;
#pragma unroll
    for (int i = 0; i < 4; i++) {
        float dx = x[i].x - mean, dy = x[i].y - mean, dz = x[i].z - mean, dw = x[i].w - mean;
        vs += dx * dx + dy * dy + dz * dz + dw * dw;
    }
#pragma unroll
    for (int o = 16; o; o >>= 1) vs += __shfl_xor_sync(0xffffffffu, vs, o);
    float invstd = rsqrtf(vs * (1.f / 512.f) + 1e-5f);

    float4* po = (float4*)(out + (size_t)row * 512);
#pragma unroll
    for (int i = 0; i < 4; i++) {
        po[l + i * 32] = make_float4((x[i].x - mean) * invstd, (x[i].y - mean) * invstd,
                                     (x[i].z - mean) * invstd, (x[i].w - mean) * invstd);
    }
}

// ---------------------------------------------------------------------------
// Launch pipeline (graph-capturable: launches only)
// ---------------------------------------------------------------------------
extern "C" void kernel_launch(void* const* d_in, const int* in_sizes, int n_in,
                              void* d_out, int out_size)
{
    const float* xl = (const float*)d_in[0];
    const float* xh = (const float*)d_in[1];
    const float* te = (const float*)d_in[2];
    const float* Wq = (const float*)d_in[3];
    const float* bq = (const float*)d_in[4];
    const float* Wk = (const float*)d_in[5];
    const float* bk = (const float*)d_in[6];
    const float* Wv = (const float*)d_in[7];
    const float* bv = (const float*)d_in[8];
    const float* Wo = (const float*)d_in[9];
    const float* bo = (const float*)d_in[10];
    const float* W1 = (const float*)d_in[11];
    const float* b1 = (const float*)d_in[12];
    const float* W2 = (const float*)d_in[13];
    const float* b2 = (const float*)d_in[14];
    float* out = (float*)d_out;

    float *s0, *s1, *s2, *s3, *s4, *wt;
    cudaGetSymbolAddress((void**)&s0, g_s0);
    cudaGetSymbolAddress((void**)&s1, g_s1);
    cudaGetSymbolAddress((void**)&s2, g_s2);
    cudaGetSymbolAddress((void**)&s3, g_s3);
    cudaGetSymbolAddress((void**)&s4, g_s4);
    cudaGetSymbolAddress((void**)&wt, g_wt);

    const dim3 tg(16, 16), tb(32, 8);
    transpose512<<<tg, tb>>>(Wq, wt + 0 * WSZ);
    transpose512<<<tg, tb>>>(Wk, wt + 1 * WSZ);
    transpose512<<<tg, tb>>>(Wv, wt + 2 * WSZ);
    transpose512<<<tg, tb>>>(Wo, wt + 3 * WSZ);
    transpose512<<<tg, tb>>>(W1, wt + 4 * WSZ);
    transpose512<<<tg, tb>>>(W2, wt + 5 * WSZ);

    const dim3 gg(4, 1024);            // N/128 x M/128 (x fastest -> A-tile L2 reuse)
    const int nadd = ELEMS / 4 / 256;

    add_te_kernel<<<nadd, 256>>>((const float4*)xl, (const float4*)xh,
                                 (const float4*)te, (float4*)s0, (float4*)s1);
    gemm_mma<<<gg, 128>>>(s0, wt + 0 * WSZ, bq, s2, 0);
    gemm_mma<<<gg, 128>>>(s1, wt + 1 * WSZ, bk, s3, 1);
    gemm_mma<<<gg, 128>>>(s1, wt + 2 * WSZ, bv, s4, 1);
    attn64<<<B_ * N_ * H_, 256>>>(s2, s3, s4, s1);
    gemm_mma<<<gg, 128>>>(s1, wt + 3 * WSZ, bo, s3, 0);
    add_ln<<<TOKENS / 8, 256>>>(s3, s0, s4);
    gemm_mma<<<gg, 128>>>(s4, wt + 4 * WSZ, b1, s2, 1);
    gemm_mma<<<gg, 128>>>(s2, wt + 5 * WSZ, b2, s0, 0);
    add_ln<<<TOKENS / 8, 256>>>(s0, s4, out);
}

// round 4
// speedup vs baseline: 2.0603x; 1.0812x over previous
#include <cuda_runtime.h>
#include <cuda_bf16.h>
#include <math.h>
#include <stdint.h>

#define B_ 8
#define T_ 64
#define N_ 256
#define H_ 8
#define D_ 64
#define FEAT 512
#define TOKENS (B_*T_*N_)          /* 131072 */
#define ELEMS  (TOKENS*FEAT)       /* 67108864 */
#define WSZ    (512*512)

// ---------------------------------------------------------------------------
// Scratch (device globals — no cudaMalloc allowed)
// fp32: s0 (xl+te -> ff2), s2 (q), s3 (k -> o), s4 (v -> val)
// bf16 hi/lo pairs: s0h/l, s1h/l, attn-out h/l, val h/l, ff1 h/l
// ---------------------------------------------------------------------------
__device__ float g_s0[ELEMS];
__device__ float g_s2[ELEMS];
__device__ float g_s3[ELEMS];
__device__ float g_s4[ELEMS];
__device__ __nv_bfloat16 g_bf[10ull * ELEMS];
__device__ __nv_bfloat16 g_wh[6 * WSZ];
__device__ __nv_bfloat16 g_wl[6 * WSZ];

// ---------------------------------------------------------------------------
// Helpers
// ---------------------------------------------------------------------------
__device__ __forceinline__ uint32_t smem_u32(const void* p) {
    uint32_t a;
    asm("{ .reg .u64 t; cvta.to.shared.u64 t, %1; cvt.u32.u64 %0, t; }" : "=r"(a) : "l"(p));
    return a;
}

__device__ __forceinline__ void cp16(uint32_t dst, const void* src) {
    asm volatile("cp.async.cg.shared.global [%0], [%1], 16;"
                 :: "r"(dst), "l"(__cvta_generic_to_global(src)));
}

__device__ __forceinline__ void ldsm4(uint32_t addr, uint32_t* r) {
    asm volatile("ldmatrix.sync.aligned.m8n8.x4.shared.b16 {%0,%1,%2,%3}, [%4];"
                 : "=r"(r[0]), "=r"(r[1]), "=r"(r[2]), "=r"(r[3]) : "r"(addr));
}

__device__ __forceinline__ void mma_bf16(float* d, const uint32_t* a,
                                         uint32_t b0, uint32_t b1) {
    asm volatile(
        "mma.sync.aligned.m16n8k16.row.col.f32.bf16.bf16.f32 "
        "{%0,%1,%2,%3}, {%4,%5,%6,%7}, {%8,%9}, {%0,%1,%2,%3};"
        : "+f"(d[0]), "+f"(d[1]), "+f"(d[2]), "+f"(d[3])
        : "r"(a[0]), "r"(a[1]), "r"(a[2]), "r"(a[3]), "r"(b0), "r"(b1));
}

// split v into hi/lo bf16 pair (packed x2)
__device__ __forceinline__ void split2(float x, float y,
                                       __nv_bfloat162& h, __nv_bfloat162& l) {
    h = __floats2bfloat162_rn(x, y);
    l = __floats2bfloat162_rn(x - __low2float(h), y - __high2float(h));
}

// ---------------------------------------------------------------------------
// Weight prep: transpose + hi/lo split. Wh/Wl[z][n][k] = split(W_z[k][n]).
// ---------------------------------------------------------------------------
__global__ __launch_bounds__(256)
void prep_w(const float* W0, const float* W1, const float* W2,
            const float* W3, const float* W4, const float* W5,
            __nv_bfloat16* __restrict__ Wh, __nv_bfloat16* __restrict__ Wl)
{
    const float* Ws[6] = {W0, W1, W2, W3, W4, W5};
    const float* W = Ws[blockIdx.z];
    __shared__ float t[32][33];
    int bx = blockIdx.x * 32, by = blockIdx.y * 32;
#pragma unroll
    for (int r = 0; r < 32; r += 8)
        t[threadIdx.y + r][threadIdx.x] =
            W[(size_t)(by + threadIdx.y + r) * 512 + bx + threadIdx.x];
    __syncthreads();
    size_t base = (size_t)blockIdx.z * WSZ;
#pragma unroll
    for (int r = 0; r < 32; r += 8) {
        float v = t[threadIdx.x][threadIdx.y + r];
        __nv_bfloat16 h = __float2bfloat16_rn(v);
        size_t o = base + (size_t)(bx + threadIdx.y + r) * 512 + by + threadIdx.x;
        Wh[o] = h;
        Wl[o] = __float2bfloat16_rn(v - __bfloat162float(h));
    }
}

// ---------------------------------------------------------------------------
// add_te0: s0 = xl + te (fp32) and hi/lo split
// add_te1: hi/lo split of (xh + te) only
// ---------------------------------------------------------------------------
__global__ __launch_bounds__(256)
void add_te0(const float4* __restrict__ xl, const float4* __restrict__ te,
             float4* __restrict__ s0,
             __nv_bfloat162* __restrict__ h, __nv_bfloat162* __restrict__ l)
{
    int i = blockIdx.x * 256 + threadIdx.x;
    float4 a = xl[i], t = te[i];
    float4 r = make_float4(a.x + t.x, a.y + t.y, a.z + t.z, a.w + t.w);
    s0[i] = r;
    __nv_bfloat162 h0, l0, h1, l1;
    split2(r.x, r.y, h0, l0);
    split2(r.z, r.w, h1, l1);
    h[2 * i] = h0; h[2 * i + 1] = h1;
    l[2 * i] = l0; l[2 * i + 1] = l1;
}

__global__ __launch_bounds__(256)
void add_te1(const float4* __restrict__ xh, const float4* __restrict__ te,
             __nv_bfloat162* __restrict__ h, __nv_bfloat162* __restrict__ l)
{
    int i = blockIdx.x * 256 + threadIdx.x;
    float4 a = xh[i], t = te[i];
    float4 r = make_float4(a.x + t.x, a.y + t.y, a.z + t.z, a.w + t.w);
    __nv_bfloat162 h0, l0, h1, l1;
    split2(r.x, r.y, h0, l0);
    split2(r.z, r.w, h1, l1);
    h[2 * i] = h0; h[2 * i + 1] = h1;
    l[2 * i] = l0; l[2 * i + 1] = l1;
}

// ---------------------------------------------------------------------------
// 3xBF16 tensor-core GEMM, pure cp.async pipeline (inputs pre-split bf16).
// C = A @ W + bias, fp32 acc. CTA 128x128, 128 thr, 4 warps (64x64 each).
// K chunks of 32; double-buffered 32KB stages (dynamic smem 64KB).
// Outputs: optional fp32 Cf, optional bf16 hi/lo Ch/Cl, optional relu.
// ---------------------------------------------------------------------------
__global__ __launch_bounds__(128, 2)
void gemm_bf3(const __nv_bfloat16* __restrict__ Ah, const __nv_bfloat16* __restrict__ Al,
              const __nv_bfloat16* __restrict__ Bh, const __nv_bfloat16* __restrict__ Bl,
              const float* __restrict__ bias,
              float* __restrict__ Cf,
              __nv_bfloat16* __restrict__ Ch, __nv_bfloat16* __restrict__ Cl,
              int relu)
{
    extern __shared__ __align__(128) unsigned char smem[];
    const uint32_t sb = smem_u32(smem);

    const int tid  = threadIdx.x;
    const int lane = tid & 31;
    const int warp = tid >> 5;
    const int wm = warp >> 1, wn = warp & 1;
    const int m0 = blockIdx.y * 128;
    const int n0 = blockIdx.x * 128;

    const __nv_bfloat16* Ahg = Ah + (size_t)m0 * 512;
    const __nv_bfloat16* Alg = Al + (size_t)m0 * 512;
    const __nv_bfloat16* Bhg = Bh + (size_t)n0 * 512;
    const __nv_bfloat16* Blg = Bl + (size_t)n0 * 512;

    // per-thread fill coordinates (4 16B chunks per matrix per stage)
    int frow[4], fc[4];
    uint32_t foff[4];
#pragma unroll
    for (int j = 0; j < 4; j++) {
        int lin = tid + j * 128;
        frow[j] = lin >> 2;
        fc[j]   = lin & 3;
        foff[j] = frow[j] * 64 + ((uint32_t)(fc[j] ^ ((frow[j] >> 1) & 3)) << 4);
    }

#define FILL(kc, st)                                                          \
    do {                                                                      \
        uint32_t s_ = sb + (st) * 32768;                                      \
        _Pragma("unroll")                                                     \
        for (int j = 0; j < 4; j++) {                                         \
            size_t g_ = (size_t)frow[j] * 512 + (kc) * 32 + fc[j] * 8;        \
            cp16(s_ + foff[j],          Ahg + g_);                            \
            cp16(s_ + 8192  + foff[j],  Alg + g_);                            \
            cp16(s_ + 16384 + foff[j],  Bhg + g_);                            \
            cp16(s_ + 24576 + foff[j],  Blg + g_);                            \
        }                                                                     \
        asm volatile("cp.async.commit_group;");                               \
    } while (0)

    float acc[4][8][4];
#pragma unroll
    for (int i = 0; i < 4; i++)
#pragma unroll
        for (int j = 0; j < 8; j++)
#pragma unroll
            for (int k = 0; k < 4; k++) acc[i][j][k] = 0.f;

    const int rA_base = wm * 64 + (lane & 7) + ((lane >> 3) & 1) * 8;
    const uint32_t kbA = ((lane >> 4) & 1) * 16;
    const int rB_base = wn * 64 + (lane & 7) + ((lane >> 4) & 1) * 8;
    const uint32_t kbB = ((lane >> 3) & 1) * 16;

    FILL(0, 0);
    FILL(1, 1);

    for (int c = 0; c < 16; c++) {
        if (c < 15) asm volatile("cp.async.wait_group 1;");
        else        asm volatile("cp.async.wait_group 0;");
        __syncthreads();

        const uint32_t st = (c & 1) * 32768;
        const uint32_t sAh = sb + st, sAl = sAh + 8192;
        const uint32_t sBh = sAh + 16384, sBl = sAh + 24576;

#pragma unroll
        for (int ks = 0; ks < 2; ks++) {
            uint32_t ah[4][4], al[4][4], bh[4][4], bl[4][4];
#pragma unroll
            for (int mt = 0; mt < 4; mt++) {
                int r = rA_base + mt * 16;
                uint32_t kb = kbA + ks * 32;
                uint32_t off = r * 64 + (kb ^ (((r >> 1) & 3) << 4));
                ldsm4(sAh + off, ah[mt]);
                ldsm4(sAl + off, al[mt]);
            }
#pragma unroll
            for (int p = 0; p < 4; p++) {
                int r = rB_base + p * 16;
                uint32_t kb = kbB + ks * 32;
                uint32_t off = r * 64 + (kb ^ (((r >> 1) & 3) << 4));
                ldsm4(sBh + off, bh[p]);
                ldsm4(sBl + off, bl[p]);
            }
#pragma unroll
            for (int mt = 0; mt < 4; mt++)
#pragma unroll
                for (int nt = 0; nt < 8; nt++) {
                    int p = nt >> 1, h = (nt & 1) * 2;
                    mma_bf16(acc[mt][nt], ah[mt], bh[p][h], bh[p][h + 1]);
                    mma_bf16(acc[mt][nt], ah[mt], bl[p][h], bl[p][h + 1]);
                    mma_bf16(acc[mt][nt], al[mt], bh[p][h], bh[p][h + 1]);
                }
        }
        __syncthreads();
        if (c + 2 < 16) FILL(c + 2, (c & 1));
    }

    // ---- epilogue ----
#pragma unroll
    for (int mt = 0; mt < 4; mt++) {
        int row = m0 + wm * 64 + mt * 16 + (lane >> 2);
#pragma unroll
        for (int nt = 0; nt < 8; nt++) {
            int col = n0 + wn * 64 + nt * 8 + (lane & 3) * 2;
            float2 bb = __ldg((const float2*)(bias + col));
            float v0 = acc[mt][nt][0] + bb.x;
            float v1 = acc[mt][nt][1] + bb.y;
            float v2 = acc[mt][nt][2] + bb.x;
            float v3 = acc[mt][nt][3] + bb.y;
            if (relu) {
                v0 = fmaxf(v0, 0.f); v1 = fmaxf(v1, 0.f);
                v2 = fmaxf(v2, 0.f); v3 = fmaxf(v3, 0.f);
            }
            if (Cf) {
                *(float2*)(Cf + (size_t)row * 512 + col)       = make_float2(v0, v1);
                *(float2*)(Cf + (size_t)(row + 8) * 512 + col) = make_float2(v2, v3);
            }
            if (Ch) {
                __nv_bfloat162 h0, l0, h1, l1;
                split2(v0, v1, h0, l0);
                split2(v2, v3, h1, l1);
                *(__nv_bfloat162*)(Ch + (size_t)row * 512 + col)       = h0;
                *(__nv_bfloat162*)(Cl + (size_t)row * 512 + col)       = l0;
                *(__nv_bfloat162*)(Ch + (size_t)(row + 8) * 512 + col) = h1;
                *(__nv_bfloat162*)(Cl + (size_t)(row + 8) * 512 + col) = l1;
            }
        }
    }
#undef FILL
}

// ---------------------------------------------------------------------------
// Causal attention per (b, n, h): T=64, D=64. Output bf16 hi/lo (feeds Wo).
// Masked BEFORE scaling: masked logit = -32767/8.
// ---------------------------------------------------------------------------
__global__ __launch_bounds__(256)
void attn64(const float* __restrict__ q, const float* __restrict__ k,
            const float* __restrict__ v,
            __nv_bfloat16* __restrict__ oh, __nv_bfloat16* __restrict__ ol)
{
    __shared__ float Qs[64 * 64];
    __shared__ float Ks[64 * 64];
    __shared__ float Vs[64 * 64];

    const int idx = blockIdx.x;
    const int h = idx & 7;
    const int n = (idx >> 3) & 255;
    const int b = idx >> 11;
    const size_t base = ((size_t)(b * T_) * N_ + n) * FEAT + h * D_;
    const int tid = threadIdx.x;
    const size_t tstride = (size_t)N_ * FEAT;

    for (int i = tid; i < 4096; i += 256) {
        int t = i >> 6, d = i & 63;
        size_t off = base + (size_t)t * tstride + d;
        Qs[i] = q[off];
        Ks[t * 64 + (d ^ (t & 31))] = k[off];
        Vs[i] = v[off];
    }
    __syncthreads();

    const int w = tid >> 5;
    const int l = tid & 31;
    const float NEG8 = -4095.875f;

#pragma unroll
    for (int r = 0; r < 8; r++) {
        int t = w * 8 + r;
        float s0 = 0.f, s1 = 0.f;
#pragma unroll
        for (int d = 0; d < 64; d++) {
            float qd = Qs[t * 64 + d];
            s0 += qd * Ks[l * 64 + (d ^ l)];
            s1 += qd * Ks[(l + 32) * 64 + (d ^ l)];
        }
        float l0 = (l      <= t) ? s0 * 0.125f : NEG8;
        float l1 = (l + 32 <= t) ? s1 * 0.125f : NEG8;
        float m = fmaxf(l0, l1);
#pragma unroll
        for (int o = 16; o; o >>= 1) m = fmaxf(m, __shfl_xor_sync(0xffffffffu, m, o));
        float e0 = __expf(l0 - m), e1 = __expf(l1 - m);
        float sum = e0 + e1;
#pragma unroll
        for (int o = 16; o; o >>= 1) sum += __shfl_xor_sync(0xffffffffu, sum, o);
        float inv = 1.f / sum;
        float p0 = e0 * inv, p1 = e1 * inv;

        float a0 = 0.f, a1 = 0.f;
#pragma unroll
        for (int s = 0; s < 32; s++) {
            float ps = __shfl_sync(0xffffffffu, p0, s);
            a0 += ps * Vs[s * 64 + l];
            a1 += ps * Vs[s * 64 + l + 32];
        }
#pragma unroll
        for (int s = 0; s < 32; s++) {
            float ps = __shfl_sync(0xffffffffu, p1, s);
            a0 += ps * Vs[(s + 32) * 64 + l];
            a1 += ps * Vs[(s + 32) * 64 + l + 32];
        }
        size_t ooff = base + (size_t)t * tstride;
        __nv_bfloat16 h0 = __float2bfloat16_rn(a0);
        __nv_bfloat16 h1 = __float2bfloat16_rn(a1);
        oh[ooff + l]      = h0;
        oh[ooff + l + 32] = h1;
        ol[ooff + l]      = __float2bfloat16_rn(a0 - __bfloat162float(h0));
        ol[ooff + l + 32] = __float2bfloat16_rn(a1 - __bfloat162float(h1));
    }
}

// ---------------------------------------------------------------------------
// out = LayerNorm(a + b); optionally also write bf16 hi/lo split of out.
// One warp per 512-dim row.
// ---------------------------------------------------------------------------
__global__ __launch_bounds__(256)
void add_ln(const float* __restrict__ a, const float* __restrict__ b,
            float* __restrict__ out,
            __nv_bfloat162* __restrict__ oh, __nv_bfloat162* __restrict__ ol)
{
    int row = blockIdx.x * 8 + (threadIdx.x >> 5);
    int l = threadIdx.x & 31;
    const float4* pa = (const float4*)(a + (size_t)row * 512);
    const float4* pb = (const float4*)(b + (size_t)row * 512);

    float4 x[4];
    float s = 0.f;
#pragma unroll
    for (int i = 0; i < 4; i++) {
        float4 u = pa[l + i * 32], w = pb[l + i * 32];
        x[i] = make_float4(u.x + w.x, u.y + w.y, u.z + w.z, u.w + w.w);
        s += x[i].x + x[i].y + x[i].z + x[i].w;
    }
#pragma unroll
    for (int o = 16; o; o >>= 1) s += __shfl_xor_sync(0xffffffffu, s, o);
    float mean = s * (1.f / 512.f);

    float vs = 0.f;
#pragma unroll
    for (int i = 0; i < 4; i++) {
        float dx = x[i].x - mean, dy = x[i].y - mean, dz = x[i].z - mean, dw = x[i].w - mean;
        vs += dx * dx + dy * dy + dz * dz + dw * dw;
    }
#pragma unroll
    for (int o = 16; o; o >>= 1) vs += __shfl_xor_sync(0xffffffffu, vs, o);
    float invstd = rsqrtf(vs * (1.f / 512.f) + 1e-5f);

    float4* po = (float4*)(out + (size_t)row * 512);
#pragma unroll
    for (int i = 0; i < 4; i++) {
        float y0 = (x[i].x - mean) * invstd, y1 = (x[i].y - mean) * invstd;
        float y2 = (x[i].z - mean) * invstd, y3 = (x[i].w - mean) * invstd;
        int fi = row * 128 + l + i * 32;
        po[l + i * 32] = make_float4(y0, y1, y2, y3);
        if (oh) {
            __nv_bfloat162 h0, l0, h1, l1;
            split2(y0, y1, h0, l0);
            split2(y2, y3, h1, l1);
            oh[2 * fi] = h0; oh[2 * fi + 1] = h1;
            ol[2 * fi] = l0; ol[2 * fi + 1] = l1;
        }
    }
}

// ---------------------------------------------------------------------------
// Launch pipeline (graph-capturable: launches only)
// ---------------------------------------------------------------------------
extern "C" void kernel_launch(void* const* d_in, const int* in_sizes, int n_in,
                              void* d_out, int out_size)
{
    const float* xl = (const float*)d_in[0];
    const float* xh = (const float*)d_in[1];
    const float* te = (const float*)d_in[2];
    const float* Wq = (const float*)d_in[3];
    const float* bq = (const float*)d_in[4];
    const float* Wk = (const float*)d_in[5];
    const float* bk = (const float*)d_in[6];
    const float* Wv = (const float*)d_in[7];
    const float* bv = (const float*)d_in[8];
    const float* Wo = (const float*)d_in[9];
    const float* bo = (const float*)d_in[10];
    const float* W1 = (const float*)d_in[11];
    const float* b1 = (const float*)d_in[12];
    const float* W2 = (const float*)d_in[13];
    const float* b2 = (const float*)d_in[14];
    float* out = (float*)d_out;

    float *s0, *s2, *s3, *s4;
    __nv_bfloat16 *bf, *wh, *wl;
    cudaGetSymbolAddress((void**)&s0, g_s0);
    cudaGetSymbolAddress((void**)&s2, g_s2);
    cudaGetSymbolAddress((void**)&s3, g_s3);
    cudaGetSymbolAddress((void**)&s4, g_s4);
    cudaGetSymbolAddress((void**)&bf, g_bf);
    cudaGetSymbolAddress((void**)&wh, g_wh);
    cudaGetSymbolAddress((void**)&wl, g_wl);

    __nv_bfloat16* s0h = bf + 0ull * ELEMS;
    __nv_bfloat16* s0l = bf + 1ull * ELEMS;
    __nv_bfloat16* s1h = bf + 2ull * ELEMS;
    __nv_bfloat16* s1l = bf + 3ull * ELEMS;
    __nv_bfloat16* aoh = bf + 4ull * ELEMS;
    __nv_bfloat16* aol = bf + 5ull * ELEMS;
    __nv_bfloat16* vh  = bf + 6ull * ELEMS;
    __nv_bfloat16* vl  = bf + 7ull * ELEMS;
    __nv_bfloat16* f1h = bf + 8ull * ELEMS;
    __nv_bfloat16* f1l = bf + 9ull * ELEMS;

    cudaFuncSetAttribute(gemm_bf3, cudaFuncAttributeMaxDynamicSharedMemorySize, 65536);

    const dim3 gg(4, 1024);            // N/128 x M/128
    const int nadd = ELEMS / 4 / 256;

    // 0: weights transpose + split
    prep_w<<<dim3(16, 16, 6), dim3(32, 8)>>>(Wq, Wk, Wv, Wo, W1, W2, wh, wl);
    // 1,2: residual adds + splits
    add_te0<<<nadd, 256>>>((const float4*)xl, (const float4*)te, (float4*)s0,
                           (__nv_bfloat162*)s0h, (__nv_bfloat162*)s0l);
    add_te1<<<nadd, 256>>>((const float4*)xh, (const float4*)te,
                           (__nv_bfloat162*)s1h, (__nv_bfloat162*)s1l);
    // 3,4,5: Q, K, V projections (launch 5 = V: ncu target)
    gemm_bf3<<<gg, 128, 65536>>>(s0h, s0l, wh + 0 * WSZ, wl + 0 * WSZ, bq, s2, 0, 0, 0);
    gemm_bf3<<<gg, 128, 65536>>>(s1h, s1l, wh + 1 * WSZ, wl + 1 * WSZ, bk, s3, 0, 0, 1);
    gemm_bf3<<<gg, 128, 65536>>>(s1h, s1l, wh + 2 * WSZ, wl + 2 * WSZ, bv, s4, 0, 0, 1);
    // 6: attention -> bf16 hi/lo
    attn64<<<B_ * N_ * H_, 256>>>(s2, s3, s4, aoh, aol);
    // 7: Wo projection -> o (s3)
    gemm_bf3<<<gg, 128, 65536>>>(aoh, aol, wh + 3 * WSZ, wl + 3 * WSZ, bo, s3, 0, 0, 0);
    // 8: val = LN(o + s0) -> s4 + split
    add_ln<<<TOKENS / 8, 256>>>(s3, s0, s4, (__nv_bfloat162*)vh, (__nv_bfloat162*)vl);
    // 9: ff1 = relu(val @ W1 + b1) -> bf16 hi/lo only
    gemm_bf3<<<gg, 128, 65536>>>(vh, vl, wh + 4 * WSZ, wl + 4 * WSZ, b1, 0, f1h, f1l, 1);
    // 10: ff2 = ff1 @ W2 + b2 -> s0
    gemm_bf3<<<gg, 128, 65536>>>(f1h, f1l, wh + 5 * WSZ, wl + 5 * WSZ, b2, s0, 0, 0, 0);
    // 11: out = LN(ff2 + val)
    add_ln<<<TOKENS / 8, 256>>>(s0, s4, out, 0, 0);
}